// round 4
// baseline (speedup 1.0000x reference)
#include <cuda_runtime.h>
#include <cstdint>

#define N_ETA 7
#define FDIM 68
#define HW (512*1024)            // 524288 pixels
#define ESTRIDE 4626             // 68*68 padded; 4626 mod 32 = 18 -> e*18 mod 32 distinct for e<7; even -> float2 aligned

__device__ unsigned char g_eta[HW];

// ---------------- threefry2x32 with key (0, 42), exactly as jax._src.prng ----------------
__device__ __forceinline__ void threefry2x32_k42(uint32_t& x0, uint32_t& x1) {
    const uint32_t K2 = 0x1BD11BDAu ^ 0u ^ 42u;
#define TFR(r) { x0 += x1; x1 = __funnelshift_l(x1, x1, (r)); x1 ^= x0; }
    /* x0 += ks[0]=0 */  x1 += 42u;
    TFR(13) TFR(15) TFR(26) TFR(6)
    x0 += 42u;  x1 += K2 + 1u;
    TFR(17) TFR(29) TFR(16) TFR(24)
    x0 += K2;   x1 += 0u + 2u;
    TFR(13) TFR(15) TFR(26) TFR(6)
    /* x0 += 0 */ x1 += 42u + 3u;
    TFR(17) TFR(29) TFR(16) TFR(24)
    x0 += 42u;  x1 += K2 + 4u;
    TFR(13) TFR(15) TFR(26) TFR(6)
    x0 += K2;   x1 += 0u + 5u;
#undef TFR
}

// uniform(tiny, 1) then gumbel, exactly replicating XLA fp32 op order
__device__ __forceinline__ float gumbel_from_bits(uint32_t bits) {
    float f = __uint_as_float((bits >> 9) | 0x3F800000u) - 1.0f;  // [0,1), exact
    const float tiny = 1.1754943508222875e-38f;
    float u = fmaxf(tiny, f + tiny);   // f*(1-tiny) rounds to f in fp32, then +tiny, then max
    return -logf(-logf(u));
}

// PARTITIONABLE threefry path (modern JAX default, jax_threefry_partitionable=True):
// element j of the [H,W,7] bits array uses 64-bit count j -> lanes (hi32(j), lo32(j)) = (0, j),
// and the 32-bit output word is out0 ^ out1.
__global__ void eta_kernel(const float* __restrict__ T, const int* __restrict__ eta) {
    __shared__ float logT[N_ETA * N_ETA];
    if (threadIdx.x < N_ETA * N_ETA)
        logT[threadIdx.x] = logf(T[threadIdx.x] + 1e-9f);
    __syncthreads();

    int p = blockIdx.x * blockDim.x + threadIdx.x;
    if (p >= HW) return;

    int r = eta[p] * N_ETA;

    float best = -3.0e38f;
    int a = 0;
#pragma unroll
    for (int k = 0; k < N_ETA; k++) {
        uint32_t x0 = 0u;                       // hi32 of 64-bit count
        uint32_t x1 = (uint32_t)(p * 7 + k);    // lo32 of 64-bit count
        threefry2x32_k42(x0, x1);
        uint32_t bits = x0 ^ x1;                // 32-bit output = xor of the two lanes
        float v = logT[r + k] + gumbel_from_bits(bits);
        if (v > best) { best = v; a = k; }      // strict > : first max wins (jnp.argmax)
    }
    g_eta[p] = (unsigned char)a;
}

// ---------------- per-pixel expert matvec: out[o,p] = sum_f W[e_p][o][f]*feat[f,p] + b[e_p][o] ----------------
__global__ __launch_bounds__(512, 1)
void compute_kernel(const float* __restrict__ feat, const float* __restrict__ W,
                    const float* __restrict__ b, float* __restrict__ out) {
    extern __shared__ float sh[];
    float* Ws = sh;                          // N_ETA * ESTRIDE
    float* bs = sh + N_ETA * ESTRIDE;        // N_ETA * FDIM

    for (int i = threadIdx.x; i < N_ETA * FDIM * FDIM; i += blockDim.x) {
        int e = i / (FDIM * FDIM);
        Ws[e * ESTRIDE + (i - e * FDIM * FDIM)] = W[i];
    }
    for (int i = threadIdx.x; i < N_ETA * FDIM; i += blockDim.x) bs[i] = b[i];
    __syncthreads();

    const int nchunks = HW / 512;            // 1024
    for (int c = blockIdx.x; c < nchunks; c += gridDim.x) {
        int p = c * 512 + threadIdx.x;
        int e = g_eta[p];
        const float* Wp = Ws + e * ESTRIDE;  // <=7 distinct SMEM bases per warp, distinct banks

        float acc[FDIM];
#pragma unroll
        for (int o = 0; o < FDIM; o++) acc[o] = bs[e * FDIM + o];

#pragma unroll 2
        for (int f = 0; f < FDIM; f += 2) {
            float v0 = feat[(size_t)f       * HW + p];
            float v1 = feat[(size_t)(f + 1) * HW + p];
#pragma unroll
            for (int o = 0; o < FDIM; o++) {
                float2 w = *reinterpret_cast<const float2*>(Wp + o * FDIM + f);
                acc[o] = fmaf(w.y, v1, fmaf(w.x, v0, acc[o]));
            }
        }
#pragma unroll
        for (int o = 0; o < FDIM; o++) out[(size_t)o * HW + p] = acc[o];
    }
}

extern "C" void kernel_launch(void* const* d_in, const int* in_sizes, int n_in,
                              void* d_out, int out_size) {
    // Resolve inputs by element count (robust to metadata ordering).
    const float* x   = 0;   // 2*34*512*1024 = 35,651,584
    const float* W   = 0;   // 7*68*68       = 32,368
    const float* b   = 0;   // 7*68          = 476
    const float* T   = 0;   // 7*7           = 49
    const int*   eta = 0;   // 512*1024      = 524,288
    for (int i = 0; i < n_in; i++) {
        switch (in_sizes[i]) {
            case 35651584: x   = (const float*)d_in[i]; break;
            case 32368:    W   = (const float*)d_in[i]; break;
            case 476:      b   = (const float*)d_in[i]; break;
            case 49:       T   = (const float*)d_in[i]; break;
            case 524288:   eta = (const int*)d_in[i];   break;
        }
    }
    float* out = (float*)d_out;                 // [68, HW]

    eta_kernel<<<HW / 256, 256>>>(T, eta);

    int smem = (N_ETA * ESTRIDE + N_ETA * FDIM) * (int)sizeof(float);  // 131,432 B
    cudaFuncSetAttribute(compute_kernel, cudaFuncAttributeMaxDynamicSharedMemorySize, smem);
    int dev = 0, sms = 148;
    cudaGetDevice(&dev);
    cudaDeviceGetAttribute(&sms, cudaDevAttrMultiProcessorCount, dev);
    compute_kernel<<<sms, 512, smem>>>(x, W, b, out);
}